// round 13
// baseline (speedup 1.0000x reference)
#include <cuda_runtime.h>
#include <cuda_fp16.h>
#include <math.h>
#include <stdint.h>

// ===========================================================================
// Live math (softmax over size-1 axis == 1 kills q/Wq/bq/rpb/k-half of Wkv):
//   h = LN(x;g1,b1); v = h@Wv+bv; y = v@Wp+bp;
//   z = y + gelu(LN(y;g2,b2)@W1+bm1)@W2 + bm2
// mma.sync m16n8k16 fp16 (fp32 accum), ldmatrix, persistent CTAs.
// R13: MT=128 tokens/tile, 512 threads (warp grid 4x4), 1 CTA/SM, ~141KB
// smem. Halves per-token barrier/phase overhead vs MT=64.
// ===========================================================================

#define CC    384
#define DD    128
#define HIDN  512
#define MT    128
#define NTHR  512
#define EPSV  1e-5f
#define PGRID 152    // persistent CTAs (1 per SM, 152 SMs)

#define WSTR  136    // K=128 tile stride (halves); row step 272B -> ldsm-clean
#define VSTR  136

// smem byte offsets
#define OFF_BB   0          // 2 x (128x136) fp16 = 69632
#define OFF_VB   69632      // v / lny : 128 x 136 fp16 = 34816
#define OFF_GB   104448     // gelu / stage-2 A chunk : 128 x 136 fp16 = 34816
#define OFF_PSUM 139264     // 512 fp32 = 2048
#define OFF_PSQ  141312     // 512 fp32 = 2048
#define OFF_MEAN 143360     // 128 fp32
#define OFF_RSTD 143872     // 128 fp32
#define OFF_CTR  144384
#define SMEM_BYTES 144512

// Pre-transposed fp16 weights, [n][k] row-major (mma row.col B operand)
__device__ __half g_WvT[DD * CC];
__device__ __half g_WpT[DD * DD];
__device__ __half g_W1T[HIDN * DD];
__device__ __half g_W2T[DD * HIDN];
__device__ int    g_ctr;

__device__ __forceinline__ uint32_t smem_u32(const void* p) {
    uint32_t a;
    asm("{ .reg .u64 t; cvta.to.shared.u64 t, %1; cvt.u32.u64 %0, t; }"
        : "=r"(a) : "l"(p));
    return a;
}
__device__ __forceinline__ void cp16(uint32_t dst, const void* src) {
    asm volatile("cp.async.cg.shared.global [%0], [%1], 16;"
                 :: "r"(dst), "l"(src));
}
__device__ __forceinline__ void cp_commit() {
    asm volatile("cp.async.commit_group;" ::: "memory");
}
template<int N> __device__ __forceinline__ void cp_wait() {
    asm volatile("cp.async.wait_group %0;" :: "n"(N) : "memory");
}
__device__ __forceinline__ void ldsm4(uint32_t r[4], uint32_t addr) {
    asm volatile("ldmatrix.sync.aligned.m8n8.x4.shared.b16 {%0,%1,%2,%3}, [%4];"
                 : "=r"(r[0]), "=r"(r[1]), "=r"(r[2]), "=r"(r[3]) : "r"(addr));
}
__device__ __forceinline__ void mma16(float c[4],
    uint32_t a0, uint32_t a1, uint32_t a2, uint32_t a3,
    uint32_t b0, uint32_t b1) {
    asm volatile(
        "mma.sync.aligned.m16n8k16.row.col.f32.f16.f16.f32 "
        "{%0,%1,%2,%3}, {%4,%5,%6,%7}, {%8,%9}, {%0,%1,%2,%3};"
        : "+f"(c[0]), "+f"(c[1]), "+f"(c[2]), "+f"(c[3])
        : "r"(a0), "r"(a1), "r"(a2), "r"(a3), "r"(b0), "r"(b1));
}

// Tanh-form gelu via sigmoid (short dep chain; dev < 2e-5 for |v|<1.5)
__device__ __forceinline__ float gelu_f(float v) {
    float v2 = v * v;
    float a  = fmaf(-0.0713548162726f, v2, -1.5957691216057f);
    float e  = __expf(v * a);
    return __fdividef(v, 1.f + e);
}

// ----- MMA body -----------------------------------------------------------
#define MMA_KSTEP(acc, aA0, aA1, aB0, aB1, koff) { \
    uint32_t a0[4], a1[4], b0[4], b1[4]; \
    ldsm4(a0, (aA0) + (koff)); ldsm4(a1, (aA1) + (koff)); \
    ldsm4(b0, (aB0) + (koff)); ldsm4(b1, (aB1) + (koff)); \
    mma16(acc[0][0], a0[0],a0[1],a0[2],a0[3], b0[0], b0[2]); \
    mma16(acc[0][1], a0[0],a0[1],a0[2],a0[3], b0[1], b0[3]); \
    mma16(acc[0][2], a0[0],a0[1],a0[2],a0[3], b1[0], b1[2]); \
    mma16(acc[0][3], a0[0],a0[1],a0[2],a0[3], b1[1], b1[3]); \
    mma16(acc[1][0], a1[0],a1[1],a1[2],a1[3], b0[0], b0[2]); \
    mma16(acc[1][1], a1[0],a1[1],a1[2],a1[3], b0[1], b0[3]); \
    mma16(acc[1][2], a1[0],a1[1],a1[2],a1[3], b1[0], b1[2]); \
    mma16(acc[1][3], a1[0],a1[1],a1[2],a1[3], b1[1], b1[3]); \
}

// K=128 GEMM: warp (wm,wn) computes rows wm*32..+31 x cols wn*32..+31
__device__ __forceinline__ void mma_gemm128(
    const __half* As, const __half* Bs,
    float acc[2][4][4], int wm, int wn, int lane)
{
    const int lrow = lane & 15;
    const int lcol = (lane >> 4) << 3;
    uint32_t aA0 = smem_u32(As + (wm * 32 +      lrow) * VSTR + lcol);
    uint32_t aA1 = smem_u32(As + (wm * 32 + 16 + lrow) * VSTR + lcol);
    uint32_t aB0 = smem_u32(Bs + (wn * 32 +      lrow) * WSTR + lcol);
    uint32_t aB1 = smem_u32(Bs + (wn * 32 + 16 + lrow) * WSTR + lcol);
    #pragma unroll
    for (int k0 = 0; k0 < 128; k0 += 16)
        MMA_KSTEP(acc, aA0, aA1, aB0, aB1, k0 * 2);
}

// ----- async B loader: 128 rows x 128 halves of Wg[n][ldw] ----------------
__device__ __forceinline__ void issueB128(__half* Bdst, const __half* __restrict__ Wg,
                                          int ldw, int tid)
{
    #pragma unroll
    for (int i = 0; i < 4; i++) {
        int idx = tid + NTHR * i;            // 2048 groups of 8 halves
        int row = idx >> 4;
        int g8  = (idx & 15) << 3;
        cp16(smem_u32(Bdst + row * WSTR + g8), Wg + row * ldw + g8);
    }
}

#define ZERO_ACC(A) { _Pragma("unroll") for (int _m=0;_m<2;_m++) \
    _Pragma("unroll") for (int _n=0;_n<4;_n++) \
    _Pragma("unroll") for (int _q=0;_q<4;_q++) (A)[_m][_n][_q] = 0.f; }

// ---------------- merged weight-prep (one launch) + counter reset ---------
__global__ void prep_all(const float* __restrict__ Wkv,
                         const float* __restrict__ Wp_,
                         const float* __restrict__ W1,
                         const float* __restrict__ W2)
{
    if (blockIdx.x == 0 && threadIdx.x == 0 && threadIdx.y == 0)
        g_ctr = 0;

    const float* src; __half* dst;
    int K, lds, coloff, kb, nb;
    int b = blockIdx.x;
    if (b < 48)       { src = Wkv; dst = g_WvT; K = CC;   lds = 256;  coloff = 128;
                        kb = b % 12;        nb = b / 12; }
    else if (b < 64)  { int i = b - 48;  src = Wp_; dst = g_WpT; K = DD;   lds = DD;
                        coloff = 0; kb = i % 4;  nb = i / 4; }
    else if (b < 128) { int i = b - 64;  src = W1;  dst = g_W1T; K = DD;   lds = HIDN;
                        coloff = 0; kb = i % 4;  nb = i / 4; }
    else              { int i = b - 128; src = W2;  dst = g_W2T; K = HIDN; lds = DD;
                        coloff = 0; kb = i % 16; nb = i / 16; }

    __shared__ float tile[32][33];
    int k0 = kb * 32, n0 = nb * 32;
    int tx = threadIdx.x, ty = threadIdx.y;
    #pragma unroll
    for (int j = 0; j < 4; j++)
        tile[ty + 8 * j][tx] = src[(k0 + ty + 8 * j) * lds + coloff + n0 + tx];
    __syncthreads();
    #pragma unroll
    for (int j = 0; j < 4; j++)
        dst[(n0 + ty + 8 * j) * K + k0 + tx] =
            __float2half_rn(tile[tx][ty + 8 * j]);
}

// ------------------------------ main kernel -------------------------------
extern __shared__ char smem_raw[];

__global__ void __launch_bounds__(NTHR, 1) fused_mma(
    const float* __restrict__ x,
    const float* __restrict__ g1, const float* __restrict__ b1,
    const float* __restrict__ bkv, const float* __restrict__ bp,
    const float* __restrict__ g2, const float* __restrict__ b2,
    const float* __restrict__ bm1, const float* __restrict__ bm2,
    float* __restrict__ out, int ntiles)
{
    __half* BwA = (__half*)(smem_raw + OFF_BB);
    __half* BwB = BwA + 128 * WSTR;
    __half* Vb  = (__half*)(smem_raw + OFF_VB);
    __half* Gb  = (__half*)(smem_raw + OFF_GB);
    __half* Ab  = (__half*)(smem_raw + OFF_GB);  // stage-2 A chunk alias
    float* psum  = (float*)(smem_raw + OFF_PSUM);
    float* psq   = (float*)(smem_raw + OFF_PSQ);
    float* smean = (float*)(smem_raw + OFF_MEAN);
    float* srstd = (float*)(smem_raw + OFF_RSTD);
    volatile int* stile = (volatile int*)(smem_raw + OFF_CTR);

    const int tid  = threadIdx.x;
    const int lane = tid & 31;
    const int warp = tid >> 5;       // 0..15
    const int wm   = warp >> 2;      // 0..3 (M tile)
    const int wn   = warp & 3;       // 0..3 (N tile)
    const int gid  = lane >> 2;
    const int tig  = lane & 3;

    for (;;) {
        if (tid == 0) *stile = atomicAdd(&g_ctr, 1);
        __syncthreads();
        int t = *stile;
        if (t >= ntiles) break;
        const long tile0 = (long)t * MT;

        // Prefetch Wv chunk0 -> BwA (hides under LN stats)
        issueB128(BwA, g_WvT, CC, tid); cp_commit();

        // ---------------- LN(x) stats (8 rows per warp) ----------------
        #pragma unroll 1
        for (int i = 0; i < 8; i++) {
            int row = warp * 8 + i;
            const float* xr = x + (tile0 + row) * CC;
            float s = 0.f, ss = 0.f;
            #pragma unroll
            for (int u = 0; u < 12; u++) {
                float tv = xr[lane + 32 * u];
                s += tv; ss += tv * tv;
            }
            #pragma unroll
            for (int o = 16; o > 0; o >>= 1) {
                s  += __shfl_xor_sync(0xffffffffu, s,  o);
                ss += __shfl_xor_sync(0xffffffffu, ss, o);
            }
            if (lane == 0) {
                float m = s * (1.f / 384.f);
                float v = ss * (1.f / 384.f) - m * m;
                smean[row] = m;
                srstd[row] = rsqrtf(v + EPSV);
            }
        }
        __syncthreads();

        // -------- v = LN(x) @ WvT : 3 x K=128 chunks, BwA/BwB ping-pong ---
        float vacc[2][4][4];
        ZERO_ACC(vacc);
        #pragma unroll 1
        for (int c = 0; c < 3; c++) {
            __half* Bcur = (c & 1) ? BwB : BwA;
            if (c == 0)      { issueB128(BwB, g_WvT + 128, CC, tid); cp_commit(); }
            else if (c == 1) { issueB128(BwA, g_WvT + 256, CC, tid); cp_commit(); }
            else             { issueB128(BwB, g_WpT, DD, tid);       cp_commit(); }

            // fill A chunk: normalize x[:, kc..kc+127] -> fp16 (128 rows)
            int kc = c * 128;
            #pragma unroll
            for (int i = 0; i < 8; i++) {
                int idx = tid + NTHR * i;        // 128 rows x 32 quads
                int row = idx >> 5, q = (idx & 31) * 4;
                int k = kc + q;
                float4 xx = *(const float4*)(x + (tile0 + row) * CC + k);
                float4 gg = *(const float4*)(g1 + k);
                float4 bb = *(const float4*)(b1 + k);
                float m = smean[row], rs = srstd[row];
                __half2 h0 = __floats2half2_rn(fmaf((xx.x - m) * rs, gg.x, bb.x),
                                               fmaf((xx.y - m) * rs, gg.y, bb.y));
                __half2 h1 = __floats2half2_rn(fmaf((xx.z - m) * rs, gg.z, bb.z),
                                               fmaf((xx.w - m) * rs, gg.w, bb.w));
                uint2 pk = make_uint2(*(uint32_t*)&h0, *(uint32_t*)&h1);
                *(uint2*)(Ab + row * VSTR + q) = pk;
            }
            cp_wait<1>();
            __syncthreads();         // chunk-c B ready; Ab published
            mma_gemm128(Ab, Bcur, vacc, wm, wn, lane);
            __syncthreads();         // all past gemm: next refills are safe
        }

        // W1(0) -> BwA (BwA free after stage-2 final sync)
        issueB128(BwA, g_W1T, DD, tid); cp_commit();

        // v epilogue -> Vb (fp16)
        #pragma unroll
        for (int mi = 0; mi < 2; mi++)
            #pragma unroll
            for (int ni = 0; ni < 4; ni++) {
                int r0 = wm * 32 + mi * 16 + gid;
                int cb = wn * 32 + ni * 8 + tig * 2;
                float b0 = bkv[128 + cb], b1v = bkv[129 + cb];
                *(__half2*)(Vb + r0 * VSTR + cb) =
                    __floats2half2_rn(vacc[mi][ni][0] + b0, vacc[mi][ni][1] + b1v);
                *(__half2*)(Vb + (r0 + 8) * VSTR + cb) =
                    __floats2half2_rn(vacc[mi][ni][2] + b0, vacc[mi][ni][3] + b1v);
            }

        // ------------- y = v @ WpT (BwB) -------------
        float yacc[2][4][4];
        ZERO_ACC(yacc);
        cp_wait<1>();                // Wp done (W1(0) may pend)
        __syncthreads();             // Vb published; BwB visible
        mma_gemm128(Vb, BwB, yacc, wm, wn, lane);

        // y epilogue: bias in regs, y -> global, LN(y) stats via shfl
        #pragma unroll
        for (int mi = 0; mi < 2; mi++)
            #pragma unroll
            for (int ni = 0; ni < 4; ni++) {
                int r0 = wm * 32 + mi * 16 + gid;
                int cb = wn * 32 + ni * 8 + tig * 2;
                float bb0 = bp[cb], bb1 = bp[cb + 1];
                yacc[mi][ni][0] += bb0;  yacc[mi][ni][1] += bb1;
                yacc[mi][ni][2] += bb0;  yacc[mi][ni][3] += bb1;
                float2 z0 = make_float2(yacc[mi][ni][0], yacc[mi][ni][1]);
                float2 z1 = make_float2(yacc[mi][ni][2], yacc[mi][ni][3]);
                *(float2*)(out + (tile0 + r0) * DD + cb)     = z0;
                *(float2*)(out + (tile0 + r0 + 8) * DD + cb) = z1;
            }
        #pragma unroll
        for (int mi = 0; mi < 2; mi++) {
            float s0 = 0.f, q0 = 0.f, s1 = 0.f, q1 = 0.f;
            #pragma unroll
            for (int ni = 0; ni < 4; ni++) {
                float a = yacc[mi][ni][0], b = yacc[mi][ni][1];
                float c = yacc[mi][ni][2], d = yacc[mi][ni][3];
                s0 += a + b;  q0 += a * a + b * b;
                s1 += c + d;  q1 += c * c + d * d;
            }
            #pragma unroll
            for (int o = 1; o <= 2; o <<= 1) {
                s0 += __shfl_xor_sync(0xffffffffu, s0, o);
                q0 += __shfl_xor_sync(0xffffffffu, q0, o);
                s1 += __shfl_xor_sync(0xffffffffu, s1, o);
                q1 += __shfl_xor_sync(0xffffffffu, q1, o);
            }
            if (tig == 0) {
                int row = wm * 32 + mi * 16 + gid;
                psum[wn * 128 + row]     = s0;  psq[wn * 128 + row]     = q0;
                psum[wn * 128 + row + 8] = s1;  psq[wn * 128 + row + 8] = q1;
            }
        }
        __syncthreads();             // psum ready; all past y gemm (BwB free)

        // lny -> Vb (fp16) from registers
        #pragma unroll
        for (int mi = 0; mi < 2; mi++) {
            int rA = wm * 32 + mi * 16 + gid;
            int rB = rA + 8;
            float mA = (psum[rA] + psum[128 + rA] + psum[256 + rA] + psum[384 + rA]) * (1.f / 128.f);
            float vA = (psq [rA] + psq [128 + rA] + psq [256 + rA] + psq [384 + rA]) * (1.f / 128.f) - mA * mA;
            float mB = (psum[rB] + psum[128 + rB] + psum[256 + rB] + psum[384 + rB]) * (1.f / 128.f);
            float vB = (psq [rB] + psq [128 + rB] + psq [256 + rB] + psq [384 + rB]) * (1.f / 128.f) - mB * mB;
            float rsA = rsqrtf(vA + EPSV), rsB = rsqrtf(vB + EPSV);
            #pragma unroll
            for (int ni = 0; ni < 4; ni++) {
                int cb = wn * 32 + ni * 8 + tig * 2;
                float gg0 = g2[cb], gg1 = g2[cb + 1];
                float bb0 = b2[cb], bb1 = b2[cb + 1];
                *(__half2*)(Vb + rA * VSTR + cb) = __floats2half2_rn(
                    fmaf((yacc[mi][ni][0] - mA) * rsA, gg0, bb0),
                    fmaf((yacc[mi][ni][1] - mA) * rsA, gg1, bb1));
                *(__half2*)(Vb + rB * VSTR + cb) = __floats2half2_rn(
                    fmaf((yacc[mi][ni][2] - mB) * rsB, gg0, bb0),
                    fmaf((yacc[mi][ni][3] - mB) * rsB, gg1, bb1));
            }
        }
        // yacc dead (y lives in global)

        // ---------- MLP: 4 hidden tiles, 2 barriers per iteration ----------
        float uacc[2][4][4];
        ZERO_ACC(uacc);
        #pragma unroll 1
        for (int cc = 0; cc < 4; cc++) {
            cp_wait<0>();            // W1(cc) in BwA done
            __syncthreads();         // lny published; prev uacc gemm done
            issueB128(BwB, g_W2T + cc * 128, HIDN, tid); cp_commit();
            float tacc[2][4][4];
            ZERO_ACC(tacc);
            mma_gemm128(Vb, BwA, tacc, wm, wn, lane);

            // gelu -> Gb (per-warp-owned regions)
            #pragma unroll
            for (int mi = 0; mi < 2; mi++)
                #pragma unroll
                for (int ni = 0; ni < 4; ni++) {
                    int r0 = wm * 32 + mi * 16 + gid;
                    int cb = wn * 32 + ni * 8 + tig * 2;
                    float bb0 = bm1[cc * 128 + cb], bb1 = bm1[cc * 128 + cb + 1];
                    *(__half2*)(Gb + r0 * VSTR + cb) = __floats2half2_rn(
                        gelu_f(tacc[mi][ni][0] + bb0),
                        gelu_f(tacc[mi][ni][1] + bb1));
                    *(__half2*)(Gb + (r0 + 8) * VSTR + cb) = __floats2half2_rn(
                        gelu_f(tacc[mi][ni][2] + bb0),
                        gelu_f(tacc[mi][ni][3] + bb1));
                }
            cp_wait<0>();            // W2(cc) in BwB done
            __syncthreads();         // Gb published; all past tacc (BwA free)
            if (cc < 3) {
                issueB128(BwA, g_W1T + (cc + 1) * 128 * DD, DD, tid);
                cp_commit();
            }
            mma_gemm128(Gb, BwB, uacc, wm, wn, lane);
        }

        // -------- z = y(reload, own addresses) + u + bm2 -> out -----------
        #pragma unroll
        for (int mi = 0; mi < 2; mi++)
            #pragma unroll
            for (int ni = 0; ni < 4; ni++) {
                int r0 = wm * 32 + mi * 16 + gid;
                int cb = wn * 32 + ni * 8 + tig * 2;
                float bb0 = bm2[cb], bb1 = bm2[cb + 1];
                float2 ya = *(float2*)(out + (tile0 + r0) * DD + cb);
                float2 yb = *(float2*)(out + (tile0 + r0 + 8) * DD + cb);
                float2 z0, z1;
                z0.x = ya.x + uacc[mi][ni][0] + bb0;
                z0.y = ya.y + uacc[mi][ni][1] + bb1;
                z1.x = yb.x + uacc[mi][ni][2] + bb0;
                z1.y = yb.y + uacc[mi][ni][3] + bb1;
                *(float2*)(out + (tile0 + r0) * DD + cb)     = z0;
                *(float2*)(out + (tile0 + r0 + 8) * DD + cb) = z1;
            }
    }
}

// ------------------------------ launcher ----------------------------------
extern "C" void kernel_launch(void* const* d_in, const int* in_sizes, int n_in,
                              void* d_out, int out_size)
{
    const float* x   = (const float*)d_in[0];
    const float* g1  = (const float*)d_in[1];
    const float* b1  = (const float*)d_in[2];
    // d_in[3]=Wq, d_in[4]=bq, d_in[7]=rpb : dead
    const float* Wkv = (const float*)d_in[5];
    const float* bkv = (const float*)d_in[6];
    const float* Wp  = (const float*)d_in[8];
    const float* bp  = (const float*)d_in[9];
    const float* g2  = (const float*)d_in[10];
    const float* b2  = (const float*)d_in[11];
    const float* W1  = (const float*)d_in[12];
    const float* bm1 = (const float*)d_in[13];
    const float* W2  = (const float*)d_in[14];
    const float* bm2 = (const float*)d_in[15];
    float* out = (float*)d_out;

    cudaFuncSetAttribute(fused_mma,
                         cudaFuncAttributeMaxDynamicSharedMemorySize,
                         SMEM_BYTES);

    prep_all<<<192, dim3(32, 8)>>>(Wkv, Wp, W1, W2);   // also resets g_ctr

    const int tokens = in_sizes[0] / CC;   // 65536
    const int ntiles = tokens / MT;        // 512
    fused_mma<<<PGRID, NTHR, SMEM_BYTES>>>(
        x, g1, b1, bkv, bp, g2, b2, bm1, bm2, out, ntiles);
}

// round 14
// speedup vs baseline: 1.1825x; 1.1825x over previous
#include <cuda_runtime.h>
#include <cuda_fp16.h>
#include <math.h>
#include <stdint.h>

// ===========================================================================
// Live math (softmax over size-1 axis == 1 kills q/Wq/bq/rpb/k-half of Wkv):
//   h = LN(x;g1,b1); v = h@Wv+bv; y = v@Wp+bp;
//   z = y + gelu(LN(y;g2,b2)@W1+bm1)@W2 + bm2
// mma.sync m16n8k16 fp16 (fp32 accum), ldmatrix, persistent CTAs,
// 64 tokens/tile, 8 warps, 2 CTAs/SM (the proven best structure).
// R14 = R12 + chunk-0 A-fill fused into the LN(x) stats pass (lanes already
// hold the x values + row stats after the shfl reduce -> write h directly).
// ===========================================================================

#define CC    384
#define DD    128
#define HIDN  512
#define MT    64
#define NTHR  256
#define EPSV  1e-5f
#define PGRID 304    // persistent CTAs (2 per SM, 152 SMs)

#define WSTR  136    // K=128 tile stride (halves); row step 272B -> ldsm-clean
#define VSTR  136

// smem byte offsets
#define OFF_BB   0          // 2 x (128x136) fp16 = 69632
#define OFF_VB   69632      // v / lny : 64 x 136 fp16 = 17408
#define OFF_GB   87040      // gelu / stage-2 A chunk : 64 x 136 fp16 = 17408
#define OFF_PSUM 104448     // 256 fp32
#define OFF_PSQ  105472     // 256 fp32
#define OFF_MEAN 106496     // 64 fp32
#define OFF_RSTD 106752     // 64 fp32
#define OFF_CTR  107008
#define SMEM_BYTES 107136

// Pre-transposed fp16 weights, [n][k] row-major (mma row.col B operand)
__device__ __half g_WvT[DD * CC];
__device__ __half g_WpT[DD * DD];
__device__ __half g_W1T[HIDN * DD];
__device__ __half g_W2T[DD * HIDN];
__device__ int    g_ctr;

__device__ __forceinline__ uint32_t smem_u32(const void* p) {
    uint32_t a;
    asm("{ .reg .u64 t; cvta.to.shared.u64 t, %1; cvt.u32.u64 %0, t; }"
        : "=r"(a) : "l"(p));
    return a;
}
__device__ __forceinline__ void cp16(uint32_t dst, const void* src) {
    asm volatile("cp.async.cg.shared.global [%0], [%1], 16;"
                 :: "r"(dst), "l"(src));
}
__device__ __forceinline__ void cp_commit() {
    asm volatile("cp.async.commit_group;" ::: "memory");
}
template<int N> __device__ __forceinline__ void cp_wait() {
    asm volatile("cp.async.wait_group %0;" :: "n"(N) : "memory");
}
__device__ __forceinline__ void ldsm4(uint32_t r[4], uint32_t addr) {
    asm volatile("ldmatrix.sync.aligned.m8n8.x4.shared.b16 {%0,%1,%2,%3}, [%4];"
                 : "=r"(r[0]), "=r"(r[1]), "=r"(r[2]), "=r"(r[3]) : "r"(addr));
}
__device__ __forceinline__ void mma16(float c[4],
    uint32_t a0, uint32_t a1, uint32_t a2, uint32_t a3,
    uint32_t b0, uint32_t b1) {
    asm volatile(
        "mma.sync.aligned.m16n8k16.row.col.f32.f16.f16.f32 "
        "{%0,%1,%2,%3}, {%4,%5,%6,%7}, {%8,%9}, {%0,%1,%2,%3};"
        : "+f"(c[0]), "+f"(c[1]), "+f"(c[2]), "+f"(c[3])
        : "r"(a0), "r"(a1), "r"(a2), "r"(a3), "r"(b0), "r"(b1));
}

// Tanh-form gelu via sigmoid (short dep chain; dev < 2e-5 for |v|<1.5)
__device__ __forceinline__ float gelu_f(float v) {
    float v2 = v * v;
    float a  = fmaf(-0.0713548162726f, v2, -1.5957691216057f);
    float e  = __expf(v * a);
    return __fdividef(v, 1.f + e);
}

// ----- MMA body -----------------------------------------------------------
#define MMA_KSTEP(acc, aA0, aA1, aB0, aB1, koff) { \
    uint32_t a0[4], a1[4], b0[4], b1[4]; \
    ldsm4(a0, (aA0) + (koff)); ldsm4(a1, (aA1) + (koff)); \
    ldsm4(b0, (aB0) + (koff)); ldsm4(b1, (aB1) + (koff)); \
    mma16(acc[0][0], a0[0],a0[1],a0[2],a0[3], b0[0], b0[2]); \
    mma16(acc[0][1], a0[0],a0[1],a0[2],a0[3], b0[1], b0[3]); \
    mma16(acc[0][2], a0[0],a0[1],a0[2],a0[3], b1[0], b1[2]); \
    mma16(acc[0][3], a0[0],a0[1],a0[2],a0[3], b1[1], b1[3]); \
    mma16(acc[1][0], a1[0],a1[1],a1[2],a1[3], b0[0], b0[2]); \
    mma16(acc[1][1], a1[0],a1[1],a1[2],a1[3], b0[1], b0[3]); \
    mma16(acc[1][2], a1[0],a1[1],a1[2],a1[3], b1[0], b1[2]); \
    mma16(acc[1][3], a1[0],a1[1],a1[2],a1[3], b1[1], b1[3]); \
}

// K=128 GEMM: A stride VSTR, B stride WSTR
__device__ __forceinline__ void mma_gemm128(
    const __half* As, const __half* Bs,
    float acc[2][4][4], int wm, int wn, int lane)
{
    const int lrow = lane & 15;
    const int lcol = (lane >> 4) << 3;
    uint32_t aA0 = smem_u32(As + (wm * 32 +      lrow) * VSTR + lcol);
    uint32_t aA1 = smem_u32(As + (wm * 32 + 16 + lrow) * VSTR + lcol);
    uint32_t aB0 = smem_u32(Bs + (wn * 32 +      lrow) * WSTR + lcol);
    uint32_t aB1 = smem_u32(Bs + (wn * 32 + 16 + lrow) * WSTR + lcol);
    #pragma unroll
    for (int k0 = 0; k0 < 128; k0 += 16)
        MMA_KSTEP(acc, aA0, aA1, aB0, aB1, k0 * 2);
}

// ----- async B loader: 128 rows x 128 halves of Wg[n][ldw] ----------------
__device__ __forceinline__ void issueB128(__half* Bdst, const __half* __restrict__ Wg,
                                          int ldw, int tid)
{
    #pragma unroll
    for (int i = 0; i < 8; i++) {
        int idx = tid + NTHR * i;
        int row = idx >> 4;
        int g8  = (idx & 15) << 3;
        cp16(smem_u32(Bdst + row * WSTR + g8), Wg + row * ldw + g8);
    }
}

#define ZERO_ACC(A) { _Pragma("unroll") for (int _m=0;_m<2;_m++) \
    _Pragma("unroll") for (int _n=0;_n<4;_n++) \
    _Pragma("unroll") for (int _q=0;_q<4;_q++) (A)[_m][_n][_q] = 0.f; }

// ---------------- merged weight-prep (one launch) + counter reset ---------
__global__ void prep_all(const float* __restrict__ Wkv,
                         const float* __restrict__ Wp_,
                         const float* __restrict__ W1,
                         const float* __restrict__ W2)
{
    if (blockIdx.x == 0 && threadIdx.x == 0 && threadIdx.y == 0)
        g_ctr = 0;

    const float* src; __half* dst;
    int K, lds, coloff, kb, nb;
    int b = blockIdx.x;
    if (b < 48)       { src = Wkv; dst = g_WvT; K = CC;   lds = 256;  coloff = 128;
                        kb = b % 12;        nb = b / 12; }
    else if (b < 64)  { int i = b - 48;  src = Wp_; dst = g_WpT; K = DD;   lds = DD;
                        coloff = 0; kb = i % 4;  nb = i / 4; }
    else if (b < 128) { int i = b - 64;  src = W1;  dst = g_W1T; K = DD;   lds = HIDN;
                        coloff = 0; kb = i % 4;  nb = i / 4; }
    else              { int i = b - 128; src = W2;  dst = g_W2T; K = HIDN; lds = DD;
                        coloff = 0; kb = i % 16; nb = i / 16; }

    __shared__ float tile[32][33];
    int k0 = kb * 32, n0 = nb * 32;
    int tx = threadIdx.x, ty = threadIdx.y;
    #pragma unroll
    for (int j = 0; j < 4; j++)
        tile[ty + 8 * j][tx] = src[(k0 + ty + 8 * j) * lds + coloff + n0 + tx];
    __syncthreads();
    #pragma unroll
    for (int j = 0; j < 4; j++)
        dst[(n0 + ty + 8 * j) * K + k0 + tx] =
            __float2half_rn(tile[tx][ty + 8 * j]);
}

// ------------------------------ main kernel -------------------------------
extern __shared__ char smem_raw[];

__global__ void __launch_bounds__(NTHR, 2) fused_mma(
    const float* __restrict__ x,
    const float* __restrict__ g1, const float* __restrict__ b1,
    const float* __restrict__ bkv, const float* __restrict__ bp,
    const float* __restrict__ g2, const float* __restrict__ b2,
    const float* __restrict__ bm1, const float* __restrict__ bm2,
    float* __restrict__ out, int ntiles)
{
    __half* BwA = (__half*)(smem_raw + OFF_BB);
    __half* BwB = BwA + 128 * WSTR;
    __half* Vb  = (__half*)(smem_raw + OFF_VB);
    __half* Gb  = (__half*)(smem_raw + OFF_GB);
    __half* Ab  = (__half*)(smem_raw + OFF_GB);  // stage-2 A chunk alias
    float* psum  = (float*)(smem_raw + OFF_PSUM);
    float* psq   = (float*)(smem_raw + OFF_PSQ);
    float* smean = (float*)(smem_raw + OFF_MEAN);
    float* srstd = (float*)(smem_raw + OFF_RSTD);
    volatile int* stile = (volatile int*)(smem_raw + OFF_CTR);

    const int tid  = threadIdx.x;
    const int lane = tid & 31;
    const int warp = tid >> 5;
    const int wm   = warp >> 2;
    const int wn   = warp & 3;
    const int gid  = lane >> 2;
    const int tig  = lane & 3;

    for (;;) {
        if (tid == 0) *stile = atomicAdd(&g_ctr, 1);
        __syncthreads();             // broadcast; all smem free for reuse
        int t = *stile;
        if (t >= ntiles) break;
        const long tile0 = (long)t * MT;

        // Prefetch Wv chunk0 -> BwA (hides under LN stats)
        issueB128(BwA, g_WvT, CC, tid); cp_commit();

        // ---- LN(x) stats + fused chunk-0 A-fill (h for k<128 from regs) --
        #pragma unroll 1
        for (int i = 0; i < 8; i++) {
            int row = warp * 8 + i;
            const float* xr = x + (tile0 + row) * CC;
            float vals[12];
            float s = 0.f, ss = 0.f;
            #pragma unroll
            for (int u = 0; u < 12; u++) {
                float tv = xr[lane + 32 * u];
                vals[u] = tv; s += tv; ss += tv * tv;
            }
            #pragma unroll
            for (int o = 16; o > 0; o >>= 1) {
                s  += __shfl_xor_sync(0xffffffffu, s,  o);
                ss += __shfl_xor_sync(0xffffffffu, ss, o);
            }
            float m  = s * (1.f / 384.f);
            float v  = ss * (1.f / 384.f) - m * m;
            float rs = rsqrtf(v + EPSV);
            if (lane == 0) { smean[row] = m; srstd[row] = rs; }
            // chunk-0 h (k = lane + 32u, u<4) straight into Ab
            #pragma unroll
            for (int u = 0; u < 4; u++) {
                int k = lane + 32 * u;
                Ab[row * VSTR + k] =
                    __float2half_rn(fmaf((vals[u] - m) * rs, g1[k], b1[k]));
            }
        }
        __syncthreads();

        // -------- v = LN(x) @ WvT : 3 x K=128 chunks, BwA/BwB ping-pong ---
        float vacc[2][4][4];
        ZERO_ACC(vacc);
        #pragma unroll 1
        for (int c = 0; c < 3; c++) {
            __half* Bcur = (c & 1) ? BwB : BwA;
            if (c == 0)      { issueB128(BwB, g_WvT + 128, CC, tid); cp_commit(); }
            else if (c == 1) { issueB128(BwA, g_WvT + 256, CC, tid); cp_commit(); }
            else             { issueB128(BwB, g_WpT, DD, tid);       cp_commit(); }

            if (c > 0) {
                // fill A chunk: normalize x[:, kc..kc+127] -> fp16
                int kc = c * 128;
                #pragma unroll
                for (int i = 0; i < 8; i++) {
                    int idx = tid + NTHR * i;        // 64 rows x 32 quads
                    int row = idx >> 5, q = (idx & 31) * 4;
                    int k = kc + q;
                    float4 xx = *(const float4*)(x + (tile0 + row) * CC + k);
                    float4 gg = *(const float4*)(g1 + k);
                    float4 bb = *(const float4*)(b1 + k);
                    float m = smean[row], rs = srstd[row];
                    __half2 h0 = __floats2half2_rn(fmaf((xx.x - m) * rs, gg.x, bb.x),
                                                   fmaf((xx.y - m) * rs, gg.y, bb.y));
                    __half2 h1 = __floats2half2_rn(fmaf((xx.z - m) * rs, gg.z, bb.z),
                                                   fmaf((xx.w - m) * rs, gg.w, bb.w));
                    uint2 pk = make_uint2(*(uint32_t*)&h0, *(uint32_t*)&h1);
                    *(uint2*)(Ab + row * VSTR + q) = pk;
                }
            }
            cp_wait<1>();
            __syncthreads();         // chunk-c B ready; Ab published
            mma_gemm128(Ab, Bcur, vacc, wm, wn, lane);
            __syncthreads();         // all past gemm: next refills are safe
        }

        // W1(0) -> BwA (BwA free after stage-2 final sync)
        issueB128(BwA, g_W1T, DD, tid); cp_commit();

        // v epilogue -> Vb (fp16)
        #pragma unroll
        for (int mi = 0; mi < 2; mi++)
            #pragma unroll
            for (int ni = 0; ni < 4; ni++) {
                int r0 = wm * 32 + mi * 16 + gid;
                int cb = wn * 32 + ni * 8 + tig * 2;
                float b0 = bkv[128 + cb], b1v = bkv[129 + cb];
                *(__half2*)(Vb + r0 * VSTR + cb) =
                    __floats2half2_rn(vacc[mi][ni][0] + b0, vacc[mi][ni][1] + b1v);
                *(__half2*)(Vb + (r0 + 8) * VSTR + cb) =
                    __floats2half2_rn(vacc[mi][ni][2] + b0, vacc[mi][ni][3] + b1v);
            }

        // ------------- y = v @ WpT (BwB) -------------
        float yacc[2][4][4];
        ZERO_ACC(yacc);
        cp_wait<1>();                // Wp done (W1(0) may pend)
        __syncthreads();             // Vb published; BwB visible
        mma_gemm128(Vb, BwB, yacc, wm, wn, lane);

        // y epilogue: bias in regs, y -> global, LN(y) stats via shfl
        #pragma unroll
        for (int mi = 0; mi < 2; mi++)
            #pragma unroll
            for (int ni = 0; ni < 4; ni++) {
                int r0 = wm * 32 + mi * 16 + gid;
                int cb = wn * 32 + ni * 8 + tig * 2;
                float bb0 = bp[cb], bb1 = bp[cb + 1];
                yacc[mi][ni][0] += bb0;  yacc[mi][ni][1] += bb1;
                yacc[mi][ni][2] += bb0;  yacc[mi][ni][3] += bb1;
                float2 z0 = make_float2(yacc[mi][ni][0], yacc[mi][ni][1]);
                float2 z1 = make_float2(yacc[mi][ni][2], yacc[mi][ni][3]);
                *(float2*)(out + (tile0 + r0) * DD + cb)     = z0;
                *(float2*)(out + (tile0 + r0 + 8) * DD + cb) = z1;
            }
        #pragma unroll
        for (int mi = 0; mi < 2; mi++) {
            float s0 = 0.f, q0 = 0.f, s1 = 0.f, q1 = 0.f;
            #pragma unroll
            for (int ni = 0; ni < 4; ni++) {
                float a = yacc[mi][ni][0], b = yacc[mi][ni][1];
                float c = yacc[mi][ni][2], d = yacc[mi][ni][3];
                s0 += a + b;  q0 += a * a + b * b;
                s1 += c + d;  q1 += c * c + d * d;
            }
            #pragma unroll
            for (int o = 1; o <= 2; o <<= 1) {
                s0 += __shfl_xor_sync(0xffffffffu, s0, o);
                q0 += __shfl_xor_sync(0xffffffffu, q0, o);
                s1 += __shfl_xor_sync(0xffffffffu, s1, o);
                q1 += __shfl_xor_sync(0xffffffffu, q1, o);
            }
            if (tig == 0) {
                int row = wm * 32 + mi * 16 + gid;
                psum[wn * 64 + row]     = s0;  psq[wn * 64 + row]     = q0;
                psum[wn * 64 + row + 8] = s1;  psq[wn * 64 + row + 8] = q1;
            }
        }
        __syncthreads();             // psum ready; all past y gemm (BwB free)

        // lny -> Vb (fp16) from registers
        #pragma unroll
        for (int mi = 0; mi < 2; mi++) {
            int rA = wm * 32 + mi * 16 + gid;
            int rB = rA + 8;
            float mA = (psum[rA] + psum[64 + rA] + psum[128 + rA] + psum[192 + rA]) * (1.f / 128.f);
            float vA = (psq [rA] + psq [64 + rA] + psq [128 + rA] + psq [192 + rA]) * (1.f / 128.f) - mA * mA;
            float mB = (psum[rB] + psum[64 + rB] + psum[128 + rB] + psum[192 + rB]) * (1.f / 128.f);
            float vB = (psq [rB] + psq [64 + rB] + psq [128 + rB] + psq [192 + rB]) * (1.f / 128.f) - mB * mB;
            float rsA = rsqrtf(vA + EPSV), rsB = rsqrtf(vB + EPSV);
            #pragma unroll
            for (int ni = 0; ni < 4; ni++) {
                int cb = wn * 32 + ni * 8 + tig * 2;
                float gg0 = g2[cb], gg1 = g2[cb + 1];
                float bb0 = b2[cb], bb1 = b2[cb + 1];
                *(__half2*)(Vb + rA * VSTR + cb) = __floats2half2_rn(
                    fmaf((yacc[mi][ni][0] - mA) * rsA, gg0, bb0),
                    fmaf((yacc[mi][ni][1] - mA) * rsA, gg1, bb1));
                *(__half2*)(Vb + rB * VSTR + cb) = __floats2half2_rn(
                    fmaf((yacc[mi][ni][2] - mB) * rsB, gg0, bb0),
                    fmaf((yacc[mi][ni][3] - mB) * rsB, gg1, bb1));
            }
        }
        // yacc dead (y lives in global)

        // ---------- MLP: 4 hidden tiles, 2 barriers per iteration ----------
        float uacc[2][4][4];
        ZERO_ACC(uacc);
        #pragma unroll 1
        for (int cc = 0; cc < 4; cc++) {
            cp_wait<0>();            // W1(cc) in BwA done
            __syncthreads();         // Vb/lny & prev Gb-read done; BwB free
            issueB128(BwB, g_W2T + cc * 128, HIDN, tid); cp_commit();
            float tacc[2][4][4];
            ZERO_ACC(tacc);
            mma_gemm128(Vb, BwA, tacc, wm, wn, lane);

            // gelu -> Gb (per-warp-owned regions; no sync needed before)
            #pragma unroll
            for (int mi = 0; mi < 2; mi++)
                #pragma unroll
                for (int ni = 0; ni < 4; ni++) {
                    int r0 = wm * 32 + mi * 16 + gid;
                    int cb = wn * 32 + ni * 8 + tig * 2;
                    float bb0 = bm1[cc * 128 + cb], bb1 = bm1[cc * 128 + cb + 1];
                    *(__half2*)(Gb + r0 * VSTR + cb) = __floats2half2_rn(
                        gelu_f(tacc[mi][ni][0] + bb0),
                        gelu_f(tacc[mi][ni][1] + bb1));
                    *(__half2*)(Gb + (r0 + 8) * VSTR + cb) = __floats2half2_rn(
                        gelu_f(tacc[mi][ni][2] + bb0),
                        gelu_f(tacc[mi][ni][3] + bb1));
                }
            cp_wait<0>();            // W2(cc) in BwB done
            __syncthreads();         // Gb published; all past tacc (BwA free)
            if (cc < 3) {
                issueB128(BwA, g_W1T + (cc + 1) * 128 * DD, DD, tid);
                cp_commit();
            }
            mma_gemm128(Gb, BwB, uacc, wm, wn, lane);
        }

        // -------- z = y(reload, own addresses) + u + bm2 -> out -----------
        #pragma unroll
        for (int mi = 0; mi < 2; mi++)
            #pragma unroll
            for (int ni = 0; ni < 4; ni++) {
                int r0 = wm * 32 + mi * 16 + gid;
                int cb = wn * 32 + ni * 8 + tig * 2;
                float bb0 = bm2[cb], bb1 = bm2[cb + 1];
                float2 ya = *(float2*)(out + (tile0 + r0) * DD + cb);
                float2 yb = *(float2*)(out + (tile0 + r0 + 8) * DD + cb);
                float2 z0, z1;
                z0.x = ya.x + uacc[mi][ni][0] + bb0;
                z0.y = ya.y + uacc[mi][ni][1] + bb1;
                z1.x = yb.x + uacc[mi][ni][2] + bb0;
                z1.y = yb.y + uacc[mi][ni][3] + bb1;
                *(float2*)(out + (tile0 + r0) * DD + cb)     = z0;
                *(float2*)(out + (tile0 + r0 + 8) * DD + cb) = z1;
            }
    }
}

// ------------------------------ launcher ----------------------------------
extern "C" void kernel_launch(void* const* d_in, const int* in_sizes, int n_in,
                              void* d_out, int out_size)
{
    const float* x   = (const float*)d_in[0];
    const float* g1  = (const float*)d_in[1];
    const float* b1  = (const float*)d_in[2];
    // d_in[3]=Wq, d_in[4]=bq, d_in[7]=rpb : dead
    const float* Wkv = (const float*)d_in[5];
    const float* bkv = (const float*)d_in[6];
    const float* Wp  = (const float*)d_in[8];
    const float* bp  = (const float*)d_in[9];
    const float* g2  = (const float*)d_in[10];
    const float* b2  = (const float*)d_in[11];
    const float* W1  = (const float*)d_in[12];
    const float* bm1 = (const float*)d_in[13];
    const float* W2  = (const float*)d_in[14];
    const float* bm2 = (const float*)d_in[15];
    float* out = (float*)d_out;

    cudaFuncSetAttribute(fused_mma,
                         cudaFuncAttributeMaxDynamicSharedMemorySize,
                         SMEM_BYTES);

    prep_all<<<192, dim3(32, 8)>>>(Wkv, Wp, W1, W2);   // also resets g_ctr

    const int tokens = in_sizes[0] / CC;   // 65536
    const int ntiles = tokens / MT;        // 1024
    fused_mma<<<PGRID, NTHR, SMEM_BYTES>>>(
        x, g1, b1, bkv, bp, g2, b2, bm1, bm2, out, ntiles);
}

// round 15
// speedup vs baseline: 1.1849x; 1.0020x over previous
#include <cuda_runtime.h>
#include <cuda_fp16.h>
#include <math.h>
#include <stdint.h>

// ===========================================================================
// Live math (softmax over size-1 axis == 1 kills q/Wq/bq/rpb/k-half of Wkv):
//   h = LN(x;g1,b1); v = h@Wv+bv; y = v@Wp+bp;
//   z = y + gelu(LN(y;g2,b2)@W1+bm1)@W2 + bm2
// mma.sync m16n8k16 fp16 (fp32 accum), ldmatrix, persistent CTAs,
// 64 tokens/tile, 8 warps, 2 CTAs/SM.
// R15 = R14 + vectorized LN(x) pass (float4 x loads, uint2 h store) +
// g1/b1 staged in smem once per CTA (fills use LDS not LDG).
// ===========================================================================

#define CC    384
#define DD    128
#define HIDN  512
#define MT    64
#define NTHR  256
#define EPSV  1e-5f
#define PGRID 304    // persistent CTAs (2 per SM, 152 SMs)

#define WSTR  136    // K=128 tile stride (halves); row step 272B -> ldsm-clean
#define VSTR  136

// smem byte offsets
#define OFF_BB   0          // 2 x (128x136) fp16 = 69632
#define OFF_VB   69632      // v / lny : 64 x 136 fp16 = 17408
#define OFF_GB   87040      // gelu / stage-2 A chunk : 64 x 136 fp16 = 17408
#define OFF_PSUM 104448     // 256 fp32
#define OFF_PSQ  105472     // 256 fp32
#define OFF_MEAN 106496     // 64 fp32
#define OFF_RSTD 106752     // 64 fp32
#define OFF_CTR  107008
#define OFF_G1S  107136     // 384 fp32 staged gamma1
#define OFF_B1S  108672     // 384 fp32 staged beta1
#define SMEM_BYTES 110208

// Pre-transposed fp16 weights, [n][k] row-major (mma row.col B operand)
__device__ __half g_WvT[DD * CC];
__device__ __half g_WpT[DD * DD];
__device__ __half g_W1T[HIDN * DD];
__device__ __half g_W2T[DD * HIDN];
__device__ int    g_ctr;

__device__ __forceinline__ uint32_t smem_u32(const void* p) {
    uint32_t a;
    asm("{ .reg .u64 t; cvta.to.shared.u64 t, %1; cvt.u32.u64 %0, t; }"
        : "=r"(a) : "l"(p));
    return a;
}
__device__ __forceinline__ void cp16(uint32_t dst, const void* src) {
    asm volatile("cp.async.cg.shared.global [%0], [%1], 16;"
                 :: "r"(dst), "l"(src));
}
__device__ __forceinline__ void cp_commit() {
    asm volatile("cp.async.commit_group;" ::: "memory");
}
template<int N> __device__ __forceinline__ void cp_wait() {
    asm volatile("cp.async.wait_group %0;" :: "n"(N) : "memory");
}
__device__ __forceinline__ void ldsm4(uint32_t r[4], uint32_t addr) {
    asm volatile("ldmatrix.sync.aligned.m8n8.x4.shared.b16 {%0,%1,%2,%3}, [%4];"
                 : "=r"(r[0]), "=r"(r[1]), "=r"(r[2]), "=r"(r[3]) : "r"(addr));
}
__device__ __forceinline__ void mma16(float c[4],
    uint32_t a0, uint32_t a1, uint32_t a2, uint32_t a3,
    uint32_t b0, uint32_t b1) {
    asm volatile(
        "mma.sync.aligned.m16n8k16.row.col.f32.f16.f16.f32 "
        "{%0,%1,%2,%3}, {%4,%5,%6,%7}, {%8,%9}, {%0,%1,%2,%3};"
        : "+f"(c[0]), "+f"(c[1]), "+f"(c[2]), "+f"(c[3])
        : "r"(a0), "r"(a1), "r"(a2), "r"(a3), "r"(b0), "r"(b1));
}

// Tanh-form gelu via sigmoid (short dep chain; dev < 2e-5 for |v|<1.5)
__device__ __forceinline__ float gelu_f(float v) {
    float v2 = v * v;
    float a  = fmaf(-0.0713548162726f, v2, -1.5957691216057f);
    float e  = __expf(v * a);
    return __fdividef(v, 1.f + e);
}

// ----- MMA body -----------------------------------------------------------
#define MMA_KSTEP(acc, aA0, aA1, aB0, aB1, koff) { \
    uint32_t a0[4], a1[4], b0[4], b1[4]; \
    ldsm4(a0, (aA0) + (koff)); ldsm4(a1, (aA1) + (koff)); \
    ldsm4(b0, (aB0) + (koff)); ldsm4(b1, (aB1) + (koff)); \
    mma16(acc[0][0], a0[0],a0[1],a0[2],a0[3], b0[0], b0[2]); \
    mma16(acc[0][1], a0[0],a0[1],a0[2],a0[3], b0[1], b0[3]); \
    mma16(acc[0][2], a0[0],a0[1],a0[2],a0[3], b1[0], b1[2]); \
    mma16(acc[0][3], a0[0],a0[1],a0[2],a0[3], b1[1], b1[3]); \
    mma16(acc[1][0], a1[0],a1[1],a1[2],a1[3], b0[0], b0[2]); \
    mma16(acc[1][1], a1[0],a1[1],a1[2],a1[3], b0[1], b0[3]); \
    mma16(acc[1][2], a1[0],a1[1],a1[2],a1[3], b1[0], b1[2]); \
    mma16(acc[1][3], a1[0],a1[1],a1[2],a1[3], b1[1], b1[3]); \
}

// K=128 GEMM: A stride VSTR, B stride WSTR
__device__ __forceinline__ void mma_gemm128(
    const __half* As, const __half* Bs,
    float acc[2][4][4], int wm, int wn, int lane)
{
    const int lrow = lane & 15;
    const int lcol = (lane >> 4) << 3;
    uint32_t aA0 = smem_u32(As + (wm * 32 +      lrow) * VSTR + lcol);
    uint32_t aA1 = smem_u32(As + (wm * 32 + 16 + lrow) * VSTR + lcol);
    uint32_t aB0 = smem_u32(Bs + (wn * 32 +      lrow) * WSTR + lcol);
    uint32_t aB1 = smem_u32(Bs + (wn * 32 + 16 + lrow) * WSTR + lcol);
    #pragma unroll
    for (int k0 = 0; k0 < 128; k0 += 16)
        MMA_KSTEP(acc, aA0, aA1, aB0, aB1, k0 * 2);
}

// ----- async B loader: 128 rows x 128 halves of Wg[n][ldw] ----------------
__device__ __forceinline__ void issueB128(__half* Bdst, const __half* __restrict__ Wg,
                                          int ldw, int tid)
{
    #pragma unroll
    for (int i = 0; i < 8; i++) {
        int idx = tid + NTHR * i;
        int row = idx >> 4;
        int g8  = (idx & 15) << 3;
        cp16(smem_u32(Bdst + row * WSTR + g8), Wg + row * ldw + g8);
    }
}

#define ZERO_ACC(A) { _Pragma("unroll") for (int _m=0;_m<2;_m++) \
    _Pragma("unroll") for (int _n=0;_n<4;_n++) \
    _Pragma("unroll") for (int _q=0;_q<4;_q++) (A)[_m][_n][_q] = 0.f; }

// ---------------- merged weight-prep (one launch) + counter reset ---------
__global__ void prep_all(const float* __restrict__ Wkv,
                         const float* __restrict__ Wp_,
                         const float* __restrict__ W1,
                         const float* __restrict__ W2)
{
    if (blockIdx.x == 0 && threadIdx.x == 0 && threadIdx.y == 0)
        g_ctr = 0;

    const float* src; __half* dst;
    int K, lds, coloff, kb, nb;
    int b = blockIdx.x;
    if (b < 48)       { src = Wkv; dst = g_WvT; K = CC;   lds = 256;  coloff = 128;
                        kb = b % 12;        nb = b / 12; }
    else if (b < 64)  { int i = b - 48;  src = Wp_; dst = g_WpT; K = DD;   lds = DD;
                        coloff = 0; kb = i % 4;  nb = i / 4; }
    else if (b < 128) { int i = b - 64;  src = W1;  dst = g_W1T; K = DD;   lds = HIDN;
                        coloff = 0; kb = i % 4;  nb = i / 4; }
    else              { int i = b - 128; src = W2;  dst = g_W2T; K = HIDN; lds = DD;
                        coloff = 0; kb = i % 16; nb = i / 16; }

    __shared__ float tile[32][33];
    int k0 = kb * 32, n0 = nb * 32;
    int tx = threadIdx.x, ty = threadIdx.y;
    #pragma unroll
    for (int j = 0; j < 4; j++)
        tile[ty + 8 * j][tx] = src[(k0 + ty + 8 * j) * lds + coloff + n0 + tx];
    __syncthreads();
    #pragma unroll
    for (int j = 0; j < 4; j++)
        dst[(n0 + ty + 8 * j) * K + k0 + tx] =
            __float2half_rn(tile[tx][ty + 8 * j]);
}

// ------------------------------ main kernel -------------------------------
extern __shared__ char smem_raw[];

__global__ void __launch_bounds__(NTHR, 2) fused_mma(
    const float* __restrict__ x,
    const float* __restrict__ g1, const float* __restrict__ b1,
    const float* __restrict__ bkv, const float* __restrict__ bp,
    const float* __restrict__ g2, const float* __restrict__ b2,
    const float* __restrict__ bm1, const float* __restrict__ bm2,
    float* __restrict__ out, int ntiles)
{
    __half* BwA = (__half*)(smem_raw + OFF_BB);
    __half* BwB = BwA + 128 * WSTR;
    __half* Vb  = (__half*)(smem_raw + OFF_VB);
    __half* Gb  = (__half*)(smem_raw + OFF_GB);
    __half* Ab  = (__half*)(smem_raw + OFF_GB);  // stage-2 A chunk alias
    float* psum  = (float*)(smem_raw + OFF_PSUM);
    float* psq   = (float*)(smem_raw + OFF_PSQ);
    float* smean = (float*)(smem_raw + OFF_MEAN);
    float* srstd = (float*)(smem_raw + OFF_RSTD);
    float* g1s   = (float*)(smem_raw + OFF_G1S);
    float* b1s   = (float*)(smem_raw + OFF_B1S);
    volatile int* stile = (volatile int*)(smem_raw + OFF_CTR);

    const int tid  = threadIdx.x;
    const int lane = tid & 31;
    const int warp = tid >> 5;
    const int wm   = warp >> 2;
    const int wn   = warp & 3;
    const int gid  = lane >> 2;
    const int tig  = lane & 3;

    // Stage g1/b1 once per CTA (visibility via loop-top barrier)
    #pragma unroll
    for (int i = tid; i < CC; i += NTHR) {
        g1s[i] = g1[i];
        b1s[i] = b1[i];
    }

    for (;;) {
        if (tid == 0) *stile = atomicAdd(&g_ctr, 1);
        __syncthreads();             // broadcast; smem free; staging visible
        int t = *stile;
        if (t >= ntiles) break;
        const long tile0 = (long)t * MT;

        // Prefetch Wv chunk0 -> BwA (hides under LN stats)
        issueB128(BwA, g_WvT, CC, tid); cp_commit();

        // ---- LN(x) stats + fused chunk-0 A-fill (vectorized) ----
        // lane owns cols {4*lane + 128u : u=0..2}; 3 x LDG.128 per row.
        #pragma unroll 1
        for (int i = 0; i < 8; i++) {
            int row = warp * 8 + i;
            const float4* xr4 = (const float4*)(x + (tile0 + row) * CC);
            float4 a0 = xr4[lane];
            float4 a1 = xr4[lane + 32];
            float4 a2 = xr4[lane + 64];
            float s  = (a0.x + a0.y) + (a0.z + a0.w)
                     + (a1.x + a1.y) + (a1.z + a1.w)
                     + (a2.x + a2.y) + (a2.z + a2.w);
            float ss = (a0.x*a0.x + a0.y*a0.y) + (a0.z*a0.z + a0.w*a0.w)
                     + (a1.x*a1.x + a1.y*a1.y) + (a1.z*a1.z + a1.w*a1.w)
                     + (a2.x*a2.x + a2.y*a2.y) + (a2.z*a2.z + a2.w*a2.w);
            #pragma unroll
            for (int o = 16; o > 0; o >>= 1) {
                s  += __shfl_xor_sync(0xffffffffu, s,  o);
                ss += __shfl_xor_sync(0xffffffffu, ss, o);
            }
            float m  = s * (1.f / 384.f);
            float v  = ss * (1.f / 384.f) - m * m;
            float rs = rsqrtf(v + EPSV);
            if (lane == 0) { smean[row] = m; srstd[row] = rs; }
            // chunk-0 h (cols 4*lane..4*lane+3) straight into Ab
            int k = lane * 4;
            float4 gg = *(const float4*)(g1s + k);
            float4 bb = *(const float4*)(b1s + k);
            __half2 h0 = __floats2half2_rn(fmaf((a0.x - m) * rs, gg.x, bb.x),
                                           fmaf((a0.y - m) * rs, gg.y, bb.y));
            __half2 h1 = __floats2half2_rn(fmaf((a0.z - m) * rs, gg.z, bb.z),
                                           fmaf((a0.w - m) * rs, gg.w, bb.w));
            uint2 pk = make_uint2(*(uint32_t*)&h0, *(uint32_t*)&h1);
            *(uint2*)(Ab + row * VSTR + k) = pk;
        }
        __syncthreads();

        // -------- v = LN(x) @ WvT : 3 x K=128 chunks, BwA/BwB ping-pong ---
        float vacc[2][4][4];
        ZERO_ACC(vacc);
        #pragma unroll 1
        for (int c = 0; c < 3; c++) {
            __half* Bcur = (c & 1) ? BwB : BwA;
            if (c == 0)      { issueB128(BwB, g_WvT + 128, CC, tid); cp_commit(); }
            else if (c == 1) { issueB128(BwA, g_WvT + 256, CC, tid); cp_commit(); }
            else             { issueB128(BwB, g_WpT, DD, tid);       cp_commit(); }

            if (c > 0) {
                // fill A chunk: normalize x[:, kc..kc+127] -> fp16
                int kc = c * 128;
                #pragma unroll
                for (int i = 0; i < 8; i++) {
                    int idx = tid + NTHR * i;        // 64 rows x 32 quads
                    int row = idx >> 5, q = (idx & 31) * 4;
                    int k = kc + q;
                    float4 xx = *(const float4*)(x + (tile0 + row) * CC + k);
                    float4 gg = *(const float4*)(g1s + k);
                    float4 bb = *(const float4*)(b1s + k);
                    float m = smean[row], rs = srstd[row];
                    __half2 h0 = __floats2half2_rn(fmaf((xx.x - m) * rs, gg.x, bb.x),
                                                   fmaf((xx.y - m) * rs, gg.y, bb.y));
                    __half2 h1 = __floats2half2_rn(fmaf((xx.z - m) * rs, gg.z, bb.z),
                                                   fmaf((xx.w - m) * rs, gg.w, bb.w));
                    uint2 pk = make_uint2(*(uint32_t*)&h0, *(uint32_t*)&h1);
                    *(uint2*)(Ab + row * VSTR + q) = pk;
                }
            }
            cp_wait<1>();
            __syncthreads();         // chunk-c B ready; Ab published
            mma_gemm128(Ab, Bcur, vacc, wm, wn, lane);
            __syncthreads();         // all past gemm: next refills are safe
        }

        // W1(0) -> BwA (BwA free after stage-2 final sync)
        issueB128(BwA, g_W1T, DD, tid); cp_commit();

        // v epilogue -> Vb (fp16)
        #pragma unroll
        for (int mi = 0; mi < 2; mi++)
            #pragma unroll
            for (int ni = 0; ni < 4; ni++) {
                int r0 = wm * 32 + mi * 16 + gid;
                int cb = wn * 32 + ni * 8 + tig * 2;
                float b0 = bkv[128 + cb], b1v = bkv[129 + cb];
                *(__half2*)(Vb + r0 * VSTR + cb) =
                    __floats2half2_rn(vacc[mi][ni][0] + b0, vacc[mi][ni][1] + b1v);
                *(__half2*)(Vb + (r0 + 8) * VSTR + cb) =
                    __floats2half2_rn(vacc[mi][ni][2] + b0, vacc[mi][ni][3] + b1v);
            }

        // ------------- y = v @ WpT (BwB) -------------
        float yacc[2][4][4];
        ZERO_ACC(yacc);
        cp_wait<1>();                // Wp done (W1(0) may pend)
        __syncthreads();             // Vb published; BwB visible
        mma_gemm128(Vb, BwB, yacc, wm, wn, lane);

        // y epilogue: bias in regs, y -> global, LN(y) stats via shfl
        #pragma unroll
        for (int mi = 0; mi < 2; mi++)
            #pragma unroll
            for (int ni = 0; ni < 4; ni++) {
                int r0 = wm * 32 + mi * 16 + gid;
                int cb = wn * 32 + ni * 8 + tig * 2;
                float bb0 = bp[cb], bb1 = bp[cb + 1];
                yacc[mi][ni][0] += bb0;  yacc[mi][ni][1] += bb1;
                yacc[mi][ni][2] += bb0;  yacc[mi][ni][3] += bb1;
                float2 z0 = make_float2(yacc[mi][ni][0], yacc[mi][ni][1]);
                float2 z1 = make_float2(yacc[mi][ni][2], yacc[mi][ni][3]);
                *(float2*)(out + (tile0 + r0) * DD + cb)     = z0;
                *(float2*)(out + (tile0 + r0 + 8) * DD + cb) = z1;
            }
        #pragma unroll
        for (int mi = 0; mi < 2; mi++) {
            float s0 = 0.f, q0 = 0.f, s1 = 0.f, q1 = 0.f;
            #pragma unroll
            for (int ni = 0; ni < 4; ni++) {
                float a = yacc[mi][ni][0], b = yacc[mi][ni][1];
                float c = yacc[mi][ni][2], d = yacc[mi][ni][3];
                s0 += a + b;  q0 += a * a + b * b;
                s1 += c + d;  q1 += c * c + d * d;
            }
            #pragma unroll
            for (int o = 1; o <= 2; o <<= 1) {
                s0 += __shfl_xor_sync(0xffffffffu, s0, o);
                q0 += __shfl_xor_sync(0xffffffffu, q0, o);
                s1 += __shfl_xor_sync(0xffffffffu, s1, o);
                q1 += __shfl_xor_sync(0xffffffffu, q1, o);
            }
            if (tig == 0) {
                int row = wm * 32 + mi * 16 + gid;
                psum[wn * 64 + row]     = s0;  psq[wn * 64 + row]     = q0;
                psum[wn * 64 + row + 8] = s1;  psq[wn * 64 + row + 8] = q1;
            }
        }
        __syncthreads();             // psum ready; all past y gemm (BwB free)

        // lny -> Vb (fp16) from registers
        #pragma unroll
        for (int mi = 0; mi < 2; mi++) {
            int rA = wm * 32 + mi * 16 + gid;
            int rB = rA + 8;
            float mA = (psum[rA] + psum[64 + rA] + psum[128 + rA] + psum[192 + rA]) * (1.f / 128.f);
            float vA = (psq [rA] + psq [64 + rA] + psq [128 + rA] + psq [192 + rA]) * (1.f / 128.f) - mA * mA;
            float mB = (psum[rB] + psum[64 + rB] + psum[128 + rB] + psum[192 + rB]) * (1.f / 128.f);
            float vB = (psq [rB] + psq [64 + rB] + psq [128 + rB] + psq [192 + rB]) * (1.f / 128.f) - mB * mB;
            float rsA = rsqrtf(vA + EPSV), rsB = rsqrtf(vB + EPSV);
            #pragma unroll
            for (int ni = 0; ni < 4; ni++) {
                int cb = wn * 32 + ni * 8 + tig * 2;
                float gg0 = g2[cb], gg1 = g2[cb + 1];
                float bb0 = b2[cb], bb1 = b2[cb + 1];
                *(__half2*)(Vb + rA * VSTR + cb) = __floats2half2_rn(
                    fmaf((yacc[mi][ni][0] - mA) * rsA, gg0, bb0),
                    fmaf((yacc[mi][ni][1] - mA) * rsA, gg1, bb1));
                *(__half2*)(Vb + rB * VSTR + cb) = __floats2half2_rn(
                    fmaf((yacc[mi][ni][2] - mB) * rsB, gg0, bb0),
                    fmaf((yacc[mi][ni][3] - mB) * rsB, gg1, bb1));
            }
        }
        // yacc dead (y lives in global)

        // ---------- MLP: 4 hidden tiles, 2 barriers per iteration ----------
        float uacc[2][4][4];
        ZERO_ACC(uacc);
        #pragma unroll 1
        for (int cc = 0; cc < 4; cc++) {
            cp_wait<0>();            // W1(cc) in BwA done
            __syncthreads();         // Vb/lny & prev Gb-read done; BwB free
            issueB128(BwB, g_W2T + cc * 128, HIDN, tid); cp_commit();
            float tacc[2][4][4];
            ZERO_ACC(tacc);
            mma_gemm128(Vb, BwA, tacc, wm, wn, lane);

            // gelu -> Gb (per-warp-owned regions; no sync needed before)
            #pragma unroll
            for (int mi = 0; mi < 2; mi++)
                #pragma unroll
                for (int ni = 0; ni < 4; ni++) {
                    int r0 = wm * 32 + mi * 16 + gid;
                    int cb = wn * 32 + ni * 8 + tig * 2;
                    float bb0 = bm1[cc * 128 + cb], bb1 = bm1[cc * 128 + cb + 1];
                    *(__half2*)(Gb + r0 * VSTR + cb) = __floats2half2_rn(
                        gelu_f(tacc[mi][ni][0] + bb0),
                        gelu_f(tacc[mi][ni][1] + bb1));
                    *(__half2*)(Gb + (r0 + 8) * VSTR + cb) = __floats2half2_rn(
                        gelu_f(tacc[mi][ni][2] + bb0),
                        gelu_f(tacc[mi][ni][3] + bb1));
                }
            cp_wait<0>();            // W2(cc) in BwB done
            __syncthreads();         // Gb published; all past tacc (BwA free)
            if (cc < 3) {
                issueB128(BwA, g_W1T + (cc + 1) * 128 * DD, DD, tid);
                cp_commit();
            }
            mma_gemm128(Gb, BwB, uacc, wm, wn, lane);
        }

        // -------- z = y(reload, own addresses) + u + bm2 -> out -----------
        #pragma unroll
        for (int mi = 0; mi < 2; mi++)
            #pragma unroll
            for (int ni = 0; ni < 4; ni++) {
                int r0 = wm * 32 + mi * 16 + gid;
                int cb = wn * 32 + ni * 8 + tig * 2;
                float bb0 = bm2[cb], bb1 = bm2[cb + 1];
                float2 ya = *(float2*)(out + (tile0 + r0) * DD + cb);
                float2 yb = *(float2*)(out + (tile0 + r0 + 8) * DD + cb);
                float2 z0, z1;
                z0.x = ya.x + uacc[mi][ni][0] + bb0;
                z0.y = ya.y + uacc[mi][ni][1] + bb1;
                z1.x = yb.x + uacc[mi][ni][2] + bb0;
                z1.y = yb.y + uacc[mi][ni][3] + bb1;
                *(float2*)(out + (tile0 + r0) * DD + cb)     = z0;
                *(float2*)(out + (tile0 + r0 + 8) * DD + cb) = z1;
            }
    }
}

// ------------------------------ launcher ----------------------------------
extern "C" void kernel_launch(void* const* d_in, const int* in_sizes, int n_in,
                              void* d_out, int out_size)
{
    const float* x   = (const float*)d_in[0];
    const float* g1  = (const float*)d_in[1];
    const float* b1  = (const float*)d_in[2];
    // d_in[3]=Wq, d_in[4]=bq, d_in[7]=rpb : dead
    const float* Wkv = (const float*)d_in[5];
    const float* bkv = (const float*)d_in[6];
    const float* Wp  = (const float*)d_in[8];
    const float* bp  = (const float*)d_in[9];
    const float* g2  = (const float*)d_in[10];
    const float* b2  = (const float*)d_in[11];
    const float* W1  = (const float*)d_in[12];
    const float* bm1 = (const float*)d_in[13];
    const float* W2  = (const float*)d_in[14];
    const float* bm2 = (const float*)d_in[15];
    float* out = (float*)d_out;

    cudaFuncSetAttribute(fused_mma,
                         cudaFuncAttributeMaxDynamicSharedMemorySize,
                         SMEM_BYTES);

    prep_all<<<192, dim3(32, 8)>>>(Wkv, Wp, W1, W2);   // also resets g_ctr

    const int tokens = in_sizes[0] / CC;   // 65536
    const int ntiles = tokens / MT;        // 1024
    fused_mma<<<PGRID, NTHR, SMEM_BYTES>>>(
        x, g1, b1, bkv, bp, g2, b2, bm1, bm2, out, ntiles);
}